// round 2
// baseline (speedup 1.0000x reference)
#include <cuda_runtime.h>
#include <cstdint>

#define N_NODES 100000
#define N_EDGES 3200000
#define D 256

// Scratch: aggregation buffer agg[r] = sum_e val_e * x[col_e]  (102.4 MB)
__device__ float g_agg[(size_t)N_NODES * D];

// ---------------------------------------------------------------------------
// Kernel 1: zero the aggregation buffer (float4 stores)
// ---------------------------------------------------------------------------
__global__ void zero_agg_kernel() {
    size_t i = (size_t)blockIdx.x * blockDim.x + threadIdx.x;
    size_t total = (size_t)N_NODES * D / 4;
    if (i < total) {
        reinterpret_cast<float4*>(g_agg)[i] = make_float4(0.f, 0.f, 0.f, 0.f);
    }
}

// ---------------------------------------------------------------------------
// Kernel 2: SpMM scatter. One warp per edge.
// Each lane handles 8 feature channels as 2x float4:
//   gather x[col] (coalesced 1KB row read), scale by val,
//   red.global.add.v4.f32 into g_agg[row] (no return value needed).
// ---------------------------------------------------------------------------
__global__ void __launch_bounds__(256) spmm_scatter_kernel(
    const float* __restrict__ x,
    const int*   __restrict__ edge_row,
    const int*   __restrict__ edge_col,
    const float* __restrict__ edge_val)
{
    int w    = (int)((blockIdx.x * (unsigned)blockDim.x + threadIdx.x) >> 5);
    int lane = threadIdx.x & 31;
    if (w >= N_EDGES) return;

    int   r = edge_row[w];
    int   c = edge_col[w];
    float v = edge_val[w];

    const float4* xr = reinterpret_cast<const float4*>(x + (size_t)c * D);
    float*        ar = g_agg + (size_t)r * D;

    float4 a0 = xr[lane];        // floats [4*lane, 4*lane+4)
    float4 a1 = xr[lane + 32];   // floats [128+4*lane, ...)

    a0.x *= v; a0.y *= v; a0.z *= v; a0.w *= v;
    a1.x *= v; a1.y *= v; a1.z *= v; a1.w *= v;

    asm volatile("red.global.add.v4.f32 [%0], {%1, %2, %3, %4};"
                 :: "l"(ar + 4 * lane), "f"(a0.x), "f"(a0.y), "f"(a0.z), "f"(a0.w)
                 : "memory");
    asm volatile("red.global.add.v4.f32 [%0], {%1, %2, %3, %4};"
                 :: "l"(ar + 128 + 4 * lane), "f"(a1.x), "f"(a1.y), "f"(a1.z), "f"(a1.w)
                 : "memory");
}

// ---------------------------------------------------------------------------
// Kernel 3: out = g_agg @ W^T + b
// Classic register-tiled SGEMM: BM=128, BN=128, BK=16, 256 threads,
// each thread computes an 8x8 register tile. A tile stored K-major
// (transposed) in smem for conflict-free column broadcast.
// NOTE: g_agg is referenced directly in device code (a __device__ symbol
// cannot be passed as a kernel argument from host code).
// ---------------------------------------------------------------------------
#define BM 128
#define BN 128
#define BK 16

__global__ void __launch_bounds__(256) gemm_bias_kernel(
    const float* __restrict__ W,      // [D, D] row-major (out, in)
    const float* __restrict__ bias,   // [D]
    float* __restrict__ out)          // [N_NODES, D]
{
    __shared__ __align__(16) float As[BK][BM];
    __shared__ __align__(16) float Bs[BK][BN];

    const float* __restrict__ A = g_agg;

    const int bm  = blockIdx.y * BM;
    const int bn  = blockIdx.x * BN;     // gridDim.x = D / BN = 2
    const int tid = threadIdx.x;
    const int tcol = tid & 15;           // 0..15  (column group, 8 cols each)
    const int trow = tid >> 4;           // 0..15  (row group, 8 rows each)

    float acc[8][8];
#pragma unroll
    for (int i = 0; i < 8; i++)
#pragma unroll
        for (int j = 0; j < 8; j++) acc[i][j] = 0.f;

    for (int k0 = 0; k0 < D; k0 += BK) {
        // Load A tile: BM x BK = 2048 floats = 512 float4, 2 per thread.
#pragma unroll
        for (int j = 0; j < 2; j++) {
            int lin = tid + j * 256;        // 0..511
            int r   = lin >> 2;             // 4 float4 per row (BK=16)
            int kq  = lin & 3;
            int grow = bm + r;
            float4 v = make_float4(0.f, 0.f, 0.f, 0.f);
            if (grow < N_NODES)
                v = *reinterpret_cast<const float4*>(A + (size_t)grow * D + k0 + kq * 4);
            As[kq * 4 + 0][r] = v.x;
            As[kq * 4 + 1][r] = v.y;
            As[kq * 4 + 2][r] = v.z;
            As[kq * 4 + 3][r] = v.w;
        }
        // Load B tile: BN x BK (rows of W), same pattern. D=256 so no bounds.
#pragma unroll
        for (int j = 0; j < 2; j++) {
            int lin = tid + j * 256;
            int r   = lin >> 2;
            int kq  = lin & 3;
            float4 v = *reinterpret_cast<const float4*>(W + (size_t)(bn + r) * D + k0 + kq * 4);
            Bs[kq * 4 + 0][r] = v.x;
            Bs[kq * 4 + 1][r] = v.y;
            Bs[kq * 4 + 2][r] = v.z;
            Bs[kq * 4 + 3][r] = v.w;
        }
        __syncthreads();

#pragma unroll
        for (int kk = 0; kk < BK; kk++) {
            float a[8], bfr[8];
            float4 a0 = *reinterpret_cast<const float4*>(&As[kk][trow * 8]);
            float4 a1 = *reinterpret_cast<const float4*>(&As[kk][trow * 8 + 4]);
            float4 b0 = *reinterpret_cast<const float4*>(&Bs[kk][tcol * 8]);
            float4 b1 = *reinterpret_cast<const float4*>(&Bs[kk][tcol * 8 + 4]);
            a[0]=a0.x; a[1]=a0.y; a[2]=a0.z; a[3]=a0.w;
            a[4]=a1.x; a[5]=a1.y; a[6]=a1.z; a[7]=a1.w;
            bfr[0]=b0.x; bfr[1]=b0.y; bfr[2]=b0.z; bfr[3]=b0.w;
            bfr[4]=b1.x; bfr[5]=b1.y; bfr[6]=b1.z; bfr[7]=b1.w;
#pragma unroll
            for (int i = 0; i < 8; i++)
#pragma unroll
                for (int j = 0; j < 8; j++)
                    acc[i][j] += a[i] * bfr[j];
        }
        __syncthreads();
    }

    // Epilogue: add bias, write coalesced float4s.
    float bv[8];
#pragma unroll
    for (int j = 0; j < 8; j++) bv[j] = bias[bn + tcol * 8 + j];

#pragma unroll
    for (int i = 0; i < 8; i++) {
        int grow = bm + trow * 8 + i;
        if (grow >= N_NODES) continue;
        float4 o0, o1;
        o0.x = acc[i][0] + bv[0]; o0.y = acc[i][1] + bv[1];
        o0.z = acc[i][2] + bv[2]; o0.w = acc[i][3] + bv[3];
        o1.x = acc[i][4] + bv[4]; o1.y = acc[i][5] + bv[5];
        o1.z = acc[i][6] + bv[6]; o1.w = acc[i][7] + bv[7];
        float* op = out + (size_t)grow * D + bn + tcol * 8;
        *reinterpret_cast<float4*>(op)     = o0;
        *reinterpret_cast<float4*>(op + 4) = o1;
    }
}

// ---------------------------------------------------------------------------
// Launch
// ---------------------------------------------------------------------------
extern "C" void kernel_launch(void* const* d_in, const int* in_sizes, int n_in,
                              void* d_out, int out_size) {
    const float* x        = (const float*)d_in[0];
    const int*   edge_row = (const int*)  d_in[1];
    const int*   edge_col = (const int*)  d_in[2];
    const float* edge_val = (const float*)d_in[3];
    const float* W        = (const float*)d_in[4];
    const float* b        = (const float*)d_in[5];
    float*       out      = (float*)d_out;

    // 1) zero agg
    {
        size_t total = (size_t)N_NODES * D / 4;
        int threads = 256;
        int blocks = (int)((total + threads - 1) / threads);
        zero_agg_kernel<<<blocks, threads>>>();
    }
    // 2) SpMM scatter: one warp per edge, 8 warps per block
    {
        int threads = 256;
        int blocks = (N_EDGES + 7) / 8;   // 400000
        spmm_scatter_kernel<<<blocks, threads>>>(x, edge_row, edge_col, edge_val);
    }
    // 3) GEMM + bias
    {
        dim3 grid(D / BN, (N_NODES + BM - 1) / BM);   // (2, 782)
        gemm_bias_kernel<<<grid, 256>>>(W, b, out);
    }
}

// round 3
// speedup vs baseline: 1.8215x; 1.8215x over previous
#include <cuda_runtime.h>
#include <cstdint>

#define N_NODES 100000
#define N_EDGES 3200000
#define D 256
#define SCAN_B 1024
#define NB ((N_NODES + SCAN_B - 1) / SCAN_B)   // 98

// ---------------------------------------------------------------------------
// Scratch (static device allocations only)
// ---------------------------------------------------------------------------
__device__ float g_y[(size_t)N_NODES * D];        // y = x @ W^T   (102.4 MB)
__device__ int2  g_csr[N_EDGES];                  // (col, val-bits) grouped by row (25.6 MB)
__device__ int   g_cnt[N_NODES];                  // per-row degree
__device__ int   g_off[N_NODES + 1];              // CSR row offsets
__device__ int   g_cur[N_NODES];                  // fill cursors
__device__ int   g_bsum[NB];                      // scan block sums
__device__ int   g_boff[NB];                      // scanned block sums

// ---------------------------------------------------------------------------
// GEMM: g_y = x @ W^T   (no bias; bias applied in the gather kernel)
// 128x128x16 register-tiled SGEMM, 256 threads, 8x8 per-thread tile.
// ---------------------------------------------------------------------------
#define BM 128
#define BN 128
#define BK 16

__global__ void __launch_bounds__(256) gemm_kernel(
    const float* __restrict__ A,      // x [N_NODES, D]
    const float* __restrict__ W)      // [D, D] row-major (out, in)
{
    __shared__ __align__(16) float As[BK][BM];
    __shared__ __align__(16) float Bs[BK][BN];

    float* __restrict__ out = g_y;

    const int bm  = blockIdx.y * BM;
    const int bn  = blockIdx.x * BN;
    const int tid = threadIdx.x;
    const int tcol = tid & 15;
    const int trow = tid >> 4;

    float acc[8][8];
#pragma unroll
    for (int i = 0; i < 8; i++)
#pragma unroll
        for (int j = 0; j < 8; j++) acc[i][j] = 0.f;

    for (int k0 = 0; k0 < D; k0 += BK) {
#pragma unroll
        for (int j = 0; j < 2; j++) {
            int lin = tid + j * 256;
            int r   = lin >> 2;
            int kq  = lin & 3;
            int grow = bm + r;
            float4 v = make_float4(0.f, 0.f, 0.f, 0.f);
            if (grow < N_NODES)
                v = *reinterpret_cast<const float4*>(A + (size_t)grow * D + k0 + kq * 4);
            As[kq * 4 + 0][r] = v.x;
            As[kq * 4 + 1][r] = v.y;
            As[kq * 4 + 2][r] = v.z;
            As[kq * 4 + 3][r] = v.w;
        }
#pragma unroll
        for (int j = 0; j < 2; j++) {
            int lin = tid + j * 256;
            int r   = lin >> 2;
            int kq  = lin & 3;
            float4 v = *reinterpret_cast<const float4*>(W + (size_t)(bn + r) * D + k0 + kq * 4);
            Bs[kq * 4 + 0][r] = v.x;
            Bs[kq * 4 + 1][r] = v.y;
            Bs[kq * 4 + 2][r] = v.z;
            Bs[kq * 4 + 3][r] = v.w;
        }
        __syncthreads();

#pragma unroll
        for (int kk = 0; kk < BK; kk++) {
            float a[8], bfr[8];
            float4 a0 = *reinterpret_cast<const float4*>(&As[kk][trow * 8]);
            float4 a1 = *reinterpret_cast<const float4*>(&As[kk][trow * 8 + 4]);
            float4 b0 = *reinterpret_cast<const float4*>(&Bs[kk][tcol * 8]);
            float4 b1 = *reinterpret_cast<const float4*>(&Bs[kk][tcol * 8 + 4]);
            a[0]=a0.x; a[1]=a0.y; a[2]=a0.z; a[3]=a0.w;
            a[4]=a1.x; a[5]=a1.y; a[6]=a1.z; a[7]=a1.w;
            bfr[0]=b0.x; bfr[1]=b0.y; bfr[2]=b0.z; bfr[3]=b0.w;
            bfr[4]=b1.x; bfr[5]=b1.y; bfr[6]=b1.z; bfr[7]=b1.w;
#pragma unroll
            for (int i = 0; i < 8; i++)
#pragma unroll
                for (int j = 0; j < 8; j++)
                    acc[i][j] += a[i] * bfr[j];
        }
        __syncthreads();
    }

#pragma unroll
    for (int i = 0; i < 8; i++) {
        int grow = bm + trow * 8 + i;
        if (grow >= N_NODES) continue;
        float4 o0, o1;
        o0.x = acc[i][0]; o0.y = acc[i][1]; o0.z = acc[i][2]; o0.w = acc[i][3];
        o1.x = acc[i][4]; o1.y = acc[i][5]; o1.z = acc[i][6]; o1.w = acc[i][7];
        float* op = out + (size_t)grow * D + bn + tcol * 8;
        *reinterpret_cast<float4*>(op)     = o0;
        *reinterpret_cast<float4*>(op + 4) = o1;
    }
}

// ---------------------------------------------------------------------------
// CSR construction
// ---------------------------------------------------------------------------
__global__ void zero_cnt_kernel() {
    int i = blockIdx.x * blockDim.x + threadIdx.x;
    if (i < N_NODES) g_cnt[i] = 0;
}

__global__ void hist_kernel(const int* __restrict__ edge_row) {
    int e = blockIdx.x * blockDim.x + threadIdx.x;
    if (e < N_EDGES) atomicAdd(&g_cnt[edge_row[e]], 1);
}

// Block-level inclusive scan (Hillis-Steele) -> exclusive offsets + block sums
__global__ void scan1_kernel() {
    __shared__ int s[SCAN_B];
    int i = blockIdx.x * SCAN_B + threadIdx.x;
    int v = (i < N_NODES) ? g_cnt[i] : 0;
    s[threadIdx.x] = v;
    __syncthreads();
#pragma unroll
    for (int d = 1; d < SCAN_B; d <<= 1) {
        int t = (threadIdx.x >= d) ? s[threadIdx.x - d] : 0;
        __syncthreads();
        s[threadIdx.x] += t;
        __syncthreads();
    }
    if (i < N_NODES) g_off[i] = s[threadIdx.x] - v;   // exclusive within block
    if (threadIdx.x == SCAN_B - 1) g_bsum[blockIdx.x] = s[SCAN_B - 1];
}

__global__ void scan2_kernel() {   // scan the NB block sums (1 block, 128 thr)
    __shared__ int s[128];
    int v = (threadIdx.x < NB) ? g_bsum[threadIdx.x] : 0;
    s[threadIdx.x] = v;
    __syncthreads();
#pragma unroll
    for (int d = 1; d < 128; d <<= 1) {
        int t = (threadIdx.x >= d) ? s[threadIdx.x - d] : 0;
        __syncthreads();
        s[threadIdx.x] += t;
        __syncthreads();
    }
    if (threadIdx.x < NB) g_boff[threadIdx.x] = s[threadIdx.x] - v;
}

__global__ void scan3_kernel() {   // add block offsets; init cursors
    int i = blockIdx.x * SCAN_B + threadIdx.x;
    if (i < N_NODES) {
        int o = g_off[i] + g_boff[blockIdx.x];
        g_off[i] = o;
        g_cur[i] = o;
    }
    if (i == 0) g_off[N_NODES] = N_EDGES;
}

__global__ void fill_kernel(const int* __restrict__ edge_row,
                            const int* __restrict__ edge_col,
                            const float* __restrict__ edge_val) {
    int e = blockIdx.x * blockDim.x + threadIdx.x;
    if (e >= N_EDGES) return;
    int r = edge_row[e];
    int pos = atomicAdd(&g_cur[r], 1);
    g_csr[pos] = make_int2(edge_col[e], __float_as_int(edge_val[e]));
}

// ---------------------------------------------------------------------------
// Gather-aggregate: one warp per node.
//   out[r] = sum_{e in row r} val_e * y[col_e] + b
// Each lane owns 8 channels (2 float4). 4-edge unroll for MLP.
// ---------------------------------------------------------------------------
__global__ void __launch_bounds__(256) gather_kernel(
    const float* __restrict__ bias,
    float* __restrict__ out)
{
    int w    = (int)((blockIdx.x * (unsigned)blockDim.x + threadIdx.x) >> 5);
    int lane = threadIdx.x & 31;
    if (w >= N_NODES) return;

    int start = g_off[w];
    int end   = g_off[w + 1];

    float4 acc0 = make_float4(0.f, 0.f, 0.f, 0.f);
    float4 acc1 = make_float4(0.f, 0.f, 0.f, 0.f);

    int e = start;
    for (; e + 4 <= end; e += 4) {
        int2 p0 = g_csr[e];
        int2 p1 = g_csr[e + 1];
        int2 p2 = g_csr[e + 2];
        int2 p3 = g_csr[e + 3];
        const float4* y0 = reinterpret_cast<const float4*>(g_y + (size_t)p0.x * D);
        const float4* y1 = reinterpret_cast<const float4*>(g_y + (size_t)p1.x * D);
        const float4* y2 = reinterpret_cast<const float4*>(g_y + (size_t)p2.x * D);
        const float4* y3 = reinterpret_cast<const float4*>(g_y + (size_t)p3.x * D);
        float4 a0 = y0[lane], b0 = y0[lane + 32];
        float4 a1 = y1[lane], b1 = y1[lane + 32];
        float4 a2 = y2[lane], b2 = y2[lane + 32];
        float4 a3 = y3[lane], b3 = y3[lane + 32];
        float v0 = __int_as_float(p0.y);
        float v1 = __int_as_float(p1.y);
        float v2 = __int_as_float(p2.y);
        float v3 = __int_as_float(p3.y);
        acc0.x += v0 * a0.x; acc0.y += v0 * a0.y; acc0.z += v0 * a0.z; acc0.w += v0 * a0.w;
        acc1.x += v0 * b0.x; acc1.y += v0 * b0.y; acc1.z += v0 * b0.z; acc1.w += v0 * b0.w;
        acc0.x += v1 * a1.x; acc0.y += v1 * a1.y; acc0.z += v1 * a1.z; acc0.w += v1 * a1.w;
        acc1.x += v1 * b1.x; acc1.y += v1 * b1.y; acc1.z += v1 * b1.z; acc1.w += v1 * b1.w;
        acc0.x += v2 * a2.x; acc0.y += v2 * a2.y; acc0.z += v2 * a2.z; acc0.w += v2 * a2.w;
        acc1.x += v2 * b2.x; acc1.y += v2 * b2.y; acc1.z += v2 * b2.z; acc1.w += v2 * b2.w;
        acc0.x += v3 * a3.x; acc0.y += v3 * a3.y; acc0.z += v3 * a3.z; acc0.w += v3 * a3.w;
        acc1.x += v3 * b3.x; acc1.y += v3 * b3.y; acc1.z += v3 * b3.z; acc1.w += v3 * b3.w;
    }
    for (; e < end; e++) {
        int2 p = g_csr[e];
        const float4* y = reinterpret_cast<const float4*>(g_y + (size_t)p.x * D);
        float4 a = y[lane], bq = y[lane + 32];
        float v = __int_as_float(p.y);
        acc0.x += v * a.x;  acc0.y += v * a.y;  acc0.z += v * a.z;  acc0.w += v * a.w;
        acc1.x += v * bq.x; acc1.y += v * bq.y; acc1.z += v * bq.z; acc1.w += v * bq.w;
    }

    // bias + write
    const float4* bv = reinterpret_cast<const float4*>(bias);
    float4 bb0 = bv[lane], bb1 = bv[lane + 32];
    acc0.x += bb0.x; acc0.y += bb0.y; acc0.z += bb0.z; acc0.w += bb0.w;
    acc1.x += bb1.x; acc1.y += bb1.y; acc1.z += bb1.z; acc1.w += bb1.w;

    float4* op = reinterpret_cast<float4*>(out + (size_t)w * D);
    op[lane]      = acc0;
    op[lane + 32] = acc1;
}

// ---------------------------------------------------------------------------
// Launch
// ---------------------------------------------------------------------------
extern "C" void kernel_launch(void* const* d_in, const int* in_sizes, int n_in,
                              void* d_out, int out_size) {
    const float* x        = (const float*)d_in[0];
    const int*   edge_row = (const int*)  d_in[1];
    const int*   edge_col = (const int*)  d_in[2];
    const float* edge_val = (const float*)d_in[3];
    const float* W        = (const float*)d_in[4];
    const float* b        = (const float*)d_in[5];
    float*       out      = (float*)d_out;

    // 1) GEMM: y = x @ W^T
    {
        dim3 grid(D / BN, (N_NODES + BM - 1) / BM);   // (2, 782)
        gemm_kernel<<<grid, 256>>>(x, W);
    }
    // 2) CSR build
    zero_cnt_kernel<<<(N_NODES + 255) / 256, 256>>>();
    hist_kernel<<<(N_EDGES + 255) / 256, 256>>>(edge_row);
    scan1_kernel<<<NB, SCAN_B>>>();
    scan2_kernel<<<1, 128>>>();
    scan3_kernel<<<NB, SCAN_B>>>();
    fill_kernel<<<(N_EDGES + 255) / 256, 256>>>(edge_row, edge_col, edge_val);
    // 3) Gather-aggregate + bias -> out
    {
        int warps_per_block = 8;
        int blocks = (N_NODES + warps_per_block - 1) / warps_per_block;  // 12500
        gather_kernel<<<blocks, 256>>>(b, out);
    }
}

// round 5
// speedup vs baseline: 2.8400x; 1.5591x over previous
#include <cuda_runtime.h>
#include <cuda_bf16.h>
#include <cuda_fp16.h>
#include <cstdint>

#define N_NODES 100000
#define N_EDGES 3200000
#define D 256
#define SCAN_B 1024
#define NB ((N_NODES + SCAN_B - 1) / SCAN_B)   // 98

// ---------------------------------------------------------------------------
// Scratch (static device allocations only)
// ---------------------------------------------------------------------------
__device__ __half g_y[(size_t)N_NODES * D];       // y = x @ W^T  (fp16, 51.2 MB)
__device__ int2   g_csr[N_EDGES];                 // (col, val-bits) grouped by row
__device__ int    g_cnt[N_NODES];
__device__ int    g_off[N_NODES + 1];
__device__ int    g_cur[N_NODES];
__device__ int    g_bsum[NB];
__device__ int    g_boff[NB];

__device__ __forceinline__ uint32_t smem_u32(const void* p) {
    uint32_t a;
    asm("{ .reg .u64 t; cvta.to.shared.u64 t, %1; cvt.u32.u64 %0, t; }"
        : "=r"(a) : "l"(p));
    return a;
}

#define LDM_X4(r, a)                                                        \
    asm volatile("ldmatrix.sync.aligned.m8n8.x4.shared.b16 "                \
                 "{%0,%1,%2,%3}, [%4];"                                     \
                 : "=r"((r)[0]), "=r"((r)[1]), "=r"((r)[2]), "=r"((r)[3])   \
                 : "r"(a))

#define MMA_BF16(c, a, b0, b1)                                              \
    asm volatile("mma.sync.aligned.m16n8k16.row.col.f32.bf16.bf16.f32 "     \
                 "{%0,%1,%2,%3}, {%4,%5,%6,%7}, {%8,%9}, {%0,%1,%2,%3};"    \
                 : "+f"((c)[0]), "+f"((c)[1]), "+f"((c)[2]), "+f"((c)[3])   \
                 : "r"((a)[0]), "r"((a)[1]), "r"((a)[2]), "r"((a)[3]),      \
                   "r"(b0), "r"(b1))

__device__ __forceinline__ uint32_t pack2bf(__nv_bfloat16 e0, __nv_bfloat16 e1) {
    return ((uint32_t)__bfloat16_as_ushort(e1) << 16) | __bfloat16_as_ushort(e0);
}

// ---------------------------------------------------------------------------
// GEMM: g_y = fp16( x @ W^T )   via mma.sync bf16 with hi/lo split.
// CTA: 128x128 tile, K streamed in chunks of 32. 8 warps (2 M x 4 N),
// warp tile 64x32. Smem tiles padded to 40 halves/row (conflict-free).
// Passes per k16: (Ahi,Bhi) + (Alo,Bhi) + (Ahi,Blo); dropped term ~2^-16.
// ---------------------------------------------------------------------------
#define APITCH 40    // halves per smem row (32 data + 8 pad)

__global__ void __launch_bounds__(256) gemm_mma_kernel(
    const float* __restrict__ x,
    const float* __restrict__ W)
{
    __shared__ __align__(16) __nv_bfloat16 sAhi[128 * APITCH];
    __shared__ __align__(16) __nv_bfloat16 sAlo[128 * APITCH];
    __shared__ __align__(16) __nv_bfloat16 sBhi[128 * APITCH];
    __shared__ __align__(16) __nv_bfloat16 sBlo[128 * APITCH];

    const int tid  = threadIdx.x;
    const int wid  = tid >> 5;
    const int lane = tid & 31;
    const int bm   = blockIdx.y * 128;
    const int bn   = blockIdx.x * 128;
    const int wm   = wid & 1;        // 0..1 -> 64-row group
    const int wn   = wid >> 1;       // 0..3 -> 32-col group

    const uint32_t uAhi = smem_u32(sAhi);
    const uint32_t uAlo = smem_u32(sAlo);
    const uint32_t uBhi = smem_u32(sBhi);
    const uint32_t uBlo = smem_u32(sBlo);

    float acc[4][4][4];
#pragma unroll
    for (int i = 0; i < 4; i++)
#pragma unroll
        for (int j = 0; j < 4; j++)
#pragma unroll
            for (int q = 0; q < 4; q++) acc[i][j][q] = 0.f;

    const int seg   = tid & 7;       // float4 segment within row (8 per row)
    const int rbase = tid >> 3;      // 0..31

    for (int kc = 0; kc < 8; kc++) {
        const int gk = kc * 32 + seg * 4;

        // ---- load + convert A (x rows) and B (W rows) ----
#pragma unroll
        for (int t = 0; t < 4; t++) {
            int row  = t * 32 + rbase;
            int grow = bm + row;
            if (grow >= N_NODES) grow = N_NODES - 1;   // pad rows: discarded later
            float4 va = *reinterpret_cast<const float4*>(x + (size_t)grow * D + gk);
            float4 vb = *reinterpret_cast<const float4*>(W + (size_t)(bn + row) * D + gk);

            __nv_bfloat16 ah0 = __float2bfloat16(va.x), ah1 = __float2bfloat16(va.y);
            __nv_bfloat16 ah2 = __float2bfloat16(va.z), ah3 = __float2bfloat16(va.w);
            __nv_bfloat16 al0 = __float2bfloat16(va.x - __bfloat162float(ah0));
            __nv_bfloat16 al1 = __float2bfloat16(va.y - __bfloat162float(ah1));
            __nv_bfloat16 al2 = __float2bfloat16(va.z - __bfloat162float(ah2));
            __nv_bfloat16 al3 = __float2bfloat16(va.w - __bfloat162float(ah3));

            __nv_bfloat16 bh0 = __float2bfloat16(vb.x), bh1 = __float2bfloat16(vb.y);
            __nv_bfloat16 bh2 = __float2bfloat16(vb.z), bh3 = __float2bfloat16(vb.w);
            __nv_bfloat16 bl0 = __float2bfloat16(vb.x - __bfloat162float(bh0));
            __nv_bfloat16 bl1 = __float2bfloat16(vb.y - __bfloat162float(bh1));
            __nv_bfloat16 bl2 = __float2bfloat16(vb.z - __bfloat162float(bh2));
            __nv_bfloat16 bl3 = __float2bfloat16(vb.w - __bfloat162float(bh3));

            int off = row * APITCH + seg * 4;
            *reinterpret_cast<uint2*>(sAhi + off) = make_uint2(pack2bf(ah0, ah1), pack2bf(ah2, ah3));
            *reinterpret_cast<uint2*>(sAlo + off) = make_uint2(pack2bf(al0, al1), pack2bf(al2, al3));
            *reinterpret_cast<uint2*>(sBhi + off) = make_uint2(pack2bf(bh0, bh1), pack2bf(bh2, bh3));
            *reinterpret_cast<uint2*>(sBlo + off) = make_uint2(pack2bf(bl0, bl1), pack2bf(bl2, bl3));
        }
        __syncthreads();

        // ---- MMA phase: two k16 steps ----
        const int mat  = lane >> 3;   // 0..3 (ldmatrix sub-matrix)
        const int lrow = lane & 7;
#pragma unroll
        for (int ks = 0; ks < 2; ks++) {
            const int kk = ks * 16;
            uint32_t ahi[4][4], alo[4][4], bhi[2][4], blo[2][4];

            // A fragments: matrices ordered (m0-7,k0),(m8-15,k0),(m0-7,k8),(m8-15,k8)
#pragma unroll
            for (int mt = 0; mt < 4; mt++) {
                int r = wm * 64 + mt * 16 + (mat & 1) * 8 + lrow;
                int c = kk + (mat >> 1) * 8;
                uint32_t bo = (uint32_t)(r * APITCH + c) * 2;
                LDM_X4(ahi[mt], uAhi + bo);
                LDM_X4(alo[mt], uAlo + bo);
            }
            // B fragments: matrices ordered (n0-7,k0),(n0-7,k8),(n8-15,k0),(n8-15,k8)
#pragma unroll
            for (int p = 0; p < 2; p++) {
                int r = wn * 32 + p * 16 + (mat >> 1) * 8 + lrow;
                int c = kk + (mat & 1) * 8;
                uint32_t bo = (uint32_t)(r * APITCH + c) * 2;
                LDM_X4(bhi[p], uBhi + bo);
                LDM_X4(blo[p], uBlo + bo);
            }

#pragma unroll
            for (int mt = 0; mt < 4; mt++)
#pragma unroll
                for (int p = 0; p < 2; p++)
#pragma unroll
                    for (int h = 0; h < 2; h++) {
                        int nt = p * 2 + h;
                        uint32_t b0h = bhi[p][h * 2], b1h = bhi[p][h * 2 + 1];
                        uint32_t b0l = blo[p][h * 2], b1l = blo[p][h * 2 + 1];
                        MMA_BF16(acc[mt][nt], ahi[mt], b0h, b1h);
                        MMA_BF16(acc[mt][nt], alo[mt], b0h, b1h);
                        MMA_BF16(acc[mt][nt], ahi[mt], b0l, b1l);
                    }
        }
        __syncthreads();
    }

    // ---- epilogue: fp32 acc -> fp16 y ----
    const int gr = lane >> 2;          // 0..7
    const int gc = (lane & 3) * 2;     // 0,2,4,6
#pragma unroll
    for (int mt = 0; mt < 4; mt++) {
        int m0 = bm + wm * 64 + mt * 16 + gr;
#pragma unroll
        for (int nt = 0; nt < 4; nt++) {
            int n = bn + wn * 32 + nt * 8 + gc;
            if (m0 < N_NODES) {
                __half2 h = __floats2half2_rn(acc[mt][nt][0], acc[mt][nt][1]);
                *reinterpret_cast<__half2*>(g_y + (size_t)m0 * D + n) = h;
            }
            if (m0 + 8 < N_NODES) {
                __half2 h = __floats2half2_rn(acc[mt][nt][2], acc[mt][nt][3]);
                *reinterpret_cast<__half2*>(g_y + (size_t)(m0 + 8) * D + n) = h;
            }
        }
    }
}

// ---------------------------------------------------------------------------
// CSR construction
// ---------------------------------------------------------------------------
__global__ void zero_cnt_kernel() {
    int i = blockIdx.x * blockDim.x + threadIdx.x;
    if (i < N_NODES) g_cnt[i] = 0;
}
__global__ void hist_kernel(const int* __restrict__ edge_row) {
    int e = blockIdx.x * blockDim.x + threadIdx.x;
    if (e < N_EDGES) atomicAdd(&g_cnt[edge_row[e]], 1);
}
__global__ void scan1_kernel() {
    __shared__ int s[SCAN_B];
    int i = blockIdx.x * SCAN_B + threadIdx.x;
    int v = (i < N_NODES) ? g_cnt[i] : 0;
    s[threadIdx.x] = v;
    __syncthreads();
#pragma unroll
    for (int d = 1; d < SCAN_B; d <<= 1) {
        int t = (threadIdx.x >= d) ? s[threadIdx.x - d] : 0;
        __syncthreads();
        s[threadIdx.x] += t;
        __syncthreads();
    }
    if (i < N_NODES) g_off[i] = s[threadIdx.x] - v;
    if (threadIdx.x == SCAN_B - 1) g_bsum[blockIdx.x] = s[SCAN_B - 1];
}
__global__ void scan2_kernel() {
    __shared__ int s[128];
    int v = (threadIdx.x < NB) ? g_bsum[threadIdx.x] : 0;
    s[threadIdx.x] = v;
    __syncthreads();
#pragma unroll
    for (int d = 1; d < 128; d <<= 1) {
        int t = (threadIdx.x >= d) ? s[threadIdx.x - d] : 0;
        __syncthreads();
        s[threadIdx.x] += t;
        __syncthreads();
    }
    if (threadIdx.x < NB) g_boff[threadIdx.x] = s[threadIdx.x] - v;
}
__global__ void scan3_kernel() {
    int i = blockIdx.x * SCAN_B + threadIdx.x;
    if (i < N_NODES) {
        int o = g_off[i] + g_boff[blockIdx.x];
        g_off[i] = o;
        g_cur[i] = o;
    }
    if (i == 0) g_off[N_NODES] = N_EDGES;
}
__global__ void fill_kernel(const int* __restrict__ edge_row,
                            const int* __restrict__ edge_col,
                            const float* __restrict__ edge_val) {
    int e = blockIdx.x * blockDim.x + threadIdx.x;
    if (e >= N_EDGES) return;
    int r = edge_row[e];
    int pos = atomicAdd(&g_cur[r], 1);
    g_csr[pos] = make_int2(edge_col[e], __float_as_int(edge_val[e]));
}

// ---------------------------------------------------------------------------
// Gather-aggregate: one warp per node.  out[r] = sum v_e * y[c_e] + b
// Each lane owns 8 contiguous channels: one uint4 (8 fp16) per edge.
// ---------------------------------------------------------------------------
__global__ void __launch_bounds__(256) gather_kernel(
    const float* __restrict__ bias,
    float* __restrict__ out)
{
    int w    = (int)((blockIdx.x * (unsigned)blockDim.x + threadIdx.x) >> 5);
    int lane = threadIdx.x & 31;
    if (w >= N_NODES) return;

    int start = g_off[w];
    int end   = g_off[w + 1];

    float a[8];
#pragma unroll
    for (int j = 0; j < 8; j++) a[j] = 0.f;

    int e = start;
    for (; e + 4 <= end; e += 4) {
        int2 p0 = g_csr[e],     p1 = g_csr[e + 1];
        int2 p2 = g_csr[e + 2], p3 = g_csr[e + 3];
        uint4 q0 = reinterpret_cast<const uint4*>(g_y + (size_t)p0.x * D)[lane];
        uint4 q1 = reinterpret_cast<const uint4*>(g_y + (size_t)p1.x * D)[lane];
        uint4 q2 = reinterpret_cast<const uint4*>(g_y + (size_t)p2.x * D)[lane];
        uint4 q3 = reinterpret_cast<const uint4*>(g_y + (size_t)p3.x * D)[lane];
        float v0 = __int_as_float(p0.y), v1 = __int_as_float(p1.y);
        float v2 = __int_as_float(p2.y), v3 = __int_as_float(p3.y);
#define ACC_Q(q, v) do {                                                       \
        float2 f0 = __half22float2(*reinterpret_cast<const __half2*>(&(q).x)); \
        float2 f1 = __half22float2(*reinterpret_cast<const __half2*>(&(q).y)); \
        float2 f2 = __half22float2(*reinterpret_cast<const __half2*>(&(q).z)); \
        float2 f3 = __half22float2(*reinterpret_cast<const __half2*>(&(q).w)); \
        a[0] += (v) * f0.x; a[1] += (v) * f0.y;                                \
        a[2] += (v) * f1.x; a[3] += (v) * f1.y;                                \
        a[4] += (v) * f2.x; a[5] += (v) * f2.y;                                \
        a[6] += (v) * f3.x; a[7] += (v) * f3.y; } while (0)
        ACC_Q(q0, v0); ACC_Q(q1, v1); ACC_Q(q2, v2); ACC_Q(q3, v3);
    }
    for (; e < end; e++) {
        int2 p = g_csr[e];
        uint4 q = reinterpret_cast<const uint4*>(g_y + (size_t)p.x * D)[lane];
        float v = __int_as_float(p.y);
        ACC_Q(q, v);
    }
#undef ACC_Q

    const float4* bp = reinterpret_cast<const float4*>(bias + lane * 8);
    float4 b0 = bp[0], b1 = bp[1];
    float4 o0 = make_float4(a[0] + b0.x, a[1] + b0.y, a[2] + b0.z, a[3] + b0.w);
    float4 o1 = make_float4(a[4] + b1.x, a[5] + b1.y, a[6] + b1.z, a[7] + b1.w);
    float4* op = reinterpret_cast<float4*>(out + (size_t)w * D + lane * 8);
    op[0] = o0;
    op[1] = o1;
}

// ---------------------------------------------------------------------------
// Launch
// ---------------------------------------------------------------------------
extern "C" void kernel_launch(void* const* d_in, const int* in_sizes, int n_in,
                              void* d_out, int out_size) {
    const float* x        = (const float*)d_in[0];
    const int*   edge_row = (const int*)  d_in[1];
    const int*   edge_col = (const int*)  d_in[2];
    const float* edge_val = (const float*)d_in[3];
    const float* W        = (const float*)d_in[4];
    const float* b        = (const float*)d_in[5];
    float*       out      = (float*)d_out;

    // 1) GEMM: y = fp16(x @ W^T)  (mma.sync bf16 hi/lo)
    {
        dim3 grid(D / 128, (N_NODES + 127) / 128);   // (2, 782)
        gemm_mma_kernel<<<grid, 256>>>(x, W);
    }
    // 2) CSR build
    zero_cnt_kernel<<<(N_NODES + 255) / 256, 256>>>();
    hist_kernel<<<(N_EDGES + 255) / 256, 256>>>(edge_row);
    scan1_kernel<<<NB, SCAN_B>>>();
    scan2_kernel<<<1, 128>>>();
    scan3_kernel<<<NB, SCAN_B>>>();
    fill_kernel<<<(N_EDGES + 255) / 256, 256>>>(edge_row, edge_col, edge_val);
    // 3) Gather-aggregate + bias -> out
    gather_kernel<<<(N_NODES + 7) / 8, 256>>>(b, out);
}

// round 6
// speedup vs baseline: 3.4878x; 1.2281x over previous
#include <cuda_runtime.h>
#include <cuda_bf16.h>
#include <cuda_fp16.h>
#include <cstdint>

#define N_NODES 100000
#define N_EDGES 3200000
#define D 256
#define SCAN_B 1024
#define NB ((N_NODES + SCAN_B - 1) / SCAN_B)   // 98

// ---------------------------------------------------------------------------
// Scratch (static device allocations only)
// ---------------------------------------------------------------------------
__device__ __half        g_y[(size_t)N_NODES * D];   // y = x @ W^T (fp16, 51.2 MB)
__device__ __nv_bfloat16 g_Whi[D * D];               // W split hi (128 KB)
__device__ __nv_bfloat16 g_Wlo[D * D];               // W split lo (128 KB)
__device__ int2          g_csr[N_EDGES];
__device__ int           g_cnt[N_NODES];
__device__ int           g_off[N_NODES + 1];
__device__ int           g_cur[N_NODES];
__device__ int           g_bsum[NB];
__device__ int           g_boff[NB];

__device__ __forceinline__ uint32_t smem_u32(const void* p) {
    uint32_t a;
    asm("{ .reg .u64 t; cvta.to.shared.u64 t, %1; cvt.u32.u64 %0, t; }"
        : "=r"(a) : "l"(p));
    return a;
}

#define LDM_X4(r, a)                                                        \
    asm volatile("ldmatrix.sync.aligned.m8n8.x4.shared.b16 "                \
                 "{%0,%1,%2,%3}, [%4];"                                     \
                 : "=r"((r)[0]), "=r"((r)[1]), "=r"((r)[2]), "=r"((r)[3])   \
                 : "r"(a))

#define MMA_BF16(c, a, b0, b1)                                              \
    asm volatile("mma.sync.aligned.m16n8k16.row.col.f32.bf16.bf16.f32 "     \
                 "{%0,%1,%2,%3}, {%4,%5,%6,%7}, {%8,%9}, {%0,%1,%2,%3};"    \
                 : "+f"((c)[0]), "+f"((c)[1]), "+f"((c)[2]), "+f"((c)[3])   \
                 : "r"((a)[0]), "r"((a)[1]), "r"((a)[2]), "r"((a)[3]),      \
                   "r"(b0), "r"(b1))

__device__ __forceinline__ uint32_t pack2bf(__nv_bfloat16 e0, __nv_bfloat16 e1) {
    return ((uint32_t)__bfloat16_as_ushort(e1) << 16) | __bfloat16_as_ushort(e0);
}

// ---------------------------------------------------------------------------
// W -> bf16 hi/lo precompute (one-shot, 256 KB read)
// ---------------------------------------------------------------------------
__global__ void conv_w_kernel(const float* __restrict__ W) {
    int i = blockIdx.x * blockDim.x + threadIdx.x;     // one float4 each
    float4 v = reinterpret_cast<const float4*>(W)[i];
    __nv_bfloat16 h0 = __float2bfloat16(v.x), h1 = __float2bfloat16(v.y);
    __nv_bfloat16 h2 = __float2bfloat16(v.z), h3 = __float2bfloat16(v.w);
    __nv_bfloat16 l0 = __float2bfloat16(v.x - __bfloat162float(h0));
    __nv_bfloat16 l1 = __float2bfloat16(v.y - __bfloat162float(h1));
    __nv_bfloat16 l2 = __float2bfloat16(v.z - __bfloat162float(h2));
    __nv_bfloat16 l3 = __float2bfloat16(v.w - __bfloat162float(h3));
    reinterpret_cast<uint2*>(g_Whi)[i] = make_uint2(pack2bf(h0, h1), pack2bf(h2, h3));
    reinterpret_cast<uint2*>(g_Wlo)[i] = make_uint2(pack2bf(l0, l1), pack2bf(l2, l3));
}

// ---------------------------------------------------------------------------
// GEMM: g_y = fp16( x @ W^T )  via mma.sync bf16 hi/lo, double-buffered.
// CTA 128x128, K chunks of 32 (8 iters), 8 warps (2M x 4N), warp tile 64x32.
// Pipeline: store regs->smem[buf]; sync; prefetch next kc into regs; MMA.
// One sync per iteration (mma(kc-1) < store(kc) < sync(kc) orders buf reuse).
// ---------------------------------------------------------------------------
#define APITCH 40                     // halves per smem row (32 data + 8 pad)
#define TILE_H (128 * APITCH)         // halves per tile
#define GEMM_SMEM (8 * TILE_H * 2)    // 2 stages x 4 tiles x 10240 B = 81920 B

__global__ void __launch_bounds__(256) gemm_mma_kernel(
    const float* __restrict__ x)
{
    extern __shared__ __align__(16) __nv_bfloat16 smem[];
    // layout: [stage][tile], tile order: Ahi, Alo, Bhi, Blo
    __nv_bfloat16* sAhi[2] = { smem,              smem + 4 * TILE_H };
    __nv_bfloat16* sAlo[2] = { smem + 1 * TILE_H, smem + 5 * TILE_H };
    __nv_bfloat16* sBhi[2] = { smem + 2 * TILE_H, smem + 6 * TILE_H };
    __nv_bfloat16* sBlo[2] = { smem + 3 * TILE_H, smem + 7 * TILE_H };

    const int tid  = threadIdx.x;
    const int wid  = tid >> 5;
    const int lane = tid & 31;
    const int bm   = blockIdx.y * 128;
    const int bn   = blockIdx.x * 128;
    const int wm   = wid & 1;
    const int wn   = wid >> 1;

    float acc[4][4][4];
#pragma unroll
    for (int i = 0; i < 4; i++)
#pragma unroll
        for (int j = 0; j < 4; j++)
#pragma unroll
            for (int q = 0; q < 4; q++) acc[i][j][q] = 0.f;

    const int seg   = tid & 7;        // float4 segment within 32-wide chunk
    const int rbase = tid >> 3;       // 0..31

    // prefetch registers
    float4 va[4];
    uint2  vbh[4], vbl[4];

#define PREFETCH(kc) do {                                                     \
        const int gk = (kc) * 32 + seg * 4;                                   \
        _Pragma("unroll")                                                     \
        for (int t = 0; t < 4; t++) {                                         \
            int row  = t * 32 + rbase;                                        \
            int grow = bm + row;                                              \
            if (grow >= N_NODES) grow = N_NODES - 1;                          \
            va[t] = *reinterpret_cast<const float4*>(x + (size_t)grow * D + gk); \
            size_t wo = ((size_t)(bn + row) * D + gk) >> 2;                   \
            vbh[t] = reinterpret_cast<const uint2*>(g_Whi)[wo];               \
            vbl[t] = reinterpret_cast<const uint2*>(g_Wlo)[wo];               \
        }                                                                     \
    } while (0)

    PREFETCH(0);

    for (int kc = 0; kc < 8; kc++) {
        const int buf = kc & 1;

        // ---- store prefetched regs into smem (A converted, B passthrough) ----
#pragma unroll
        for (int t = 0; t < 4; t++) {
            int row = t * 32 + rbase;
            int off = row * APITCH + seg * 4;
            float4 v = va[t];
            __nv_bfloat16 h0 = __float2bfloat16(v.x), h1 = __float2bfloat16(v.y);
            __nv_bfloat16 h2 = __float2bfloat16(v.z), h3 = __float2bfloat16(v.w);
            __nv_bfloat16 l0 = __float2bfloat16(v.x - __bfloat162float(h0));
            __nv_bfloat16 l1 = __float2bfloat16(v.y - __bfloat162float(h1));
            __nv_bfloat16 l2 = __float2bfloat16(v.z - __bfloat162float(h2));
            __nv_bfloat16 l3 = __float2bfloat16(v.w - __bfloat162float(h3));
            *reinterpret_cast<uint2*>(sAhi[buf] + off) = make_uint2(pack2bf(h0, h1), pack2bf(h2, h3));
            *reinterpret_cast<uint2*>(sAlo[buf] + off) = make_uint2(pack2bf(l0, l1), pack2bf(l2, l3));
            *reinterpret_cast<uint2*>(sBhi[buf] + off) = vbh[t];
            *reinterpret_cast<uint2*>(sBlo[buf] + off) = vbl[t];
        }
        __syncthreads();

        // ---- issue next-iteration global loads (overlap with MMA below) ----
        if (kc < 7) PREFETCH(kc + 1);

        // ---- MMA phase: two k16 steps on smem[buf] ----
        const uint32_t uAhi = smem_u32(sAhi[buf]);
        const uint32_t uAlo = smem_u32(sAlo[buf]);
        const uint32_t uBhi = smem_u32(sBhi[buf]);
        const uint32_t uBlo = smem_u32(sBlo[buf]);
        const int mat  = lane >> 3;
        const int lrow = lane & 7;
#pragma unroll
        for (int ks = 0; ks < 2; ks++) {
            const int kk = ks * 16;
            uint32_t ahi[4][4], alo[4][4], bhi[2][4], blo[2][4];
#pragma unroll
            for (int mt = 0; mt < 4; mt++) {
                int r = wm * 64 + mt * 16 + (mat & 1) * 8 + lrow;
                int c = kk + (mat >> 1) * 8;
                uint32_t bo = (uint32_t)(r * APITCH + c) * 2;
                LDM_X4(ahi[mt], uAhi + bo);
                LDM_X4(alo[mt], uAlo + bo);
            }
#pragma unroll
            for (int p = 0; p < 2; p++) {
                int r = wn * 32 + p * 16 + (mat >> 1) * 8 + lrow;
                int c = kk + (mat & 1) * 8;
                uint32_t bo = (uint32_t)(r * APITCH + c) * 2;
                LDM_X4(bhi[p], uBhi + bo);
                LDM_X4(blo[p], uBlo + bo);
            }
#pragma unroll
            for (int mt = 0; mt < 4; mt++)
#pragma unroll
                for (int p = 0; p < 2; p++)
#pragma unroll
                    for (int h = 0; h < 2; h++) {
                        int nt = p * 2 + h;
                        uint32_t b0h = bhi[p][h * 2], b1h = bhi[p][h * 2 + 1];
                        uint32_t b0l = blo[p][h * 2], b1l = blo[p][h * 2 + 1];
                        MMA_BF16(acc[mt][nt], ahi[mt], b0h, b1h);
                        MMA_BF16(acc[mt][nt], alo[mt], b0h, b1h);
                        MMA_BF16(acc[mt][nt], ahi[mt], b0l, b1l);
                    }
        }
    }
#undef PREFETCH

    // ---- epilogue: fp32 acc -> fp16 y ----
    const int gr = lane >> 2;
    const int gc = (lane & 3) * 2;
#pragma unroll
    for (int mt = 0; mt < 4; mt++) {
        int m0 = bm + wm * 64 + mt * 16 + gr;
#pragma unroll
        for (int nt = 0; nt < 4; nt++) {
            int n = bn + wn * 32 + nt * 8 + gc;
            if (m0 < N_NODES) {
                __half2 h = __floats2half2_rn(acc[mt][nt][0], acc[mt][nt][1]);
                *reinterpret_cast<__half2*>(g_y + (size_t)m0 * D + n) = h;
            }
            if (m0 + 8 < N_NODES) {
                __half2 h = __floats2half2_rn(acc[mt][nt][2], acc[mt][nt][3]);
                *reinterpret_cast<__half2*>(g_y + (size_t)(m0 + 8) * D + n) = h;
            }
        }
    }
}

// ---------------------------------------------------------------------------
// CSR construction
// ---------------------------------------------------------------------------
__global__ void zero_cnt_kernel() {
    int i = blockIdx.x * blockDim.x + threadIdx.x;
    if (i < N_NODES) g_cnt[i] = 0;
}
__global__ void hist_kernel(const int* __restrict__ edge_row) {
    int e = blockIdx.x * blockDim.x + threadIdx.x;
    if (e < N_EDGES) atomicAdd(&g_cnt[edge_row[e]], 1);
}
__global__ void scan1_kernel() {
    __shared__ int s[SCAN_B];
    int i = blockIdx.x * SCAN_B + threadIdx.x;
    int v = (i < N_NODES) ? g_cnt[i] : 0;
    s[threadIdx.x] = v;
    __syncthreads();
#pragma unroll
    for (int d = 1; d < SCAN_B; d <<= 1) {
        int t = (threadIdx.x >= d) ? s[threadIdx.x - d] : 0;
        __syncthreads();
        s[threadIdx.x] += t;
        __syncthreads();
    }
    if (i < N_NODES) g_off[i] = s[threadIdx.x] - v;
    if (threadIdx.x == SCAN_B - 1) g_bsum[blockIdx.x] = s[SCAN_B - 1];
}
__global__ void scan2_kernel() {
    __shared__ int s[128];
    int v = (threadIdx.x < NB) ? g_bsum[threadIdx.x] : 0;
    s[threadIdx.x] = v;
    __syncthreads();
#pragma unroll
    for (int d = 1; d < 128; d <<= 1) {
        int t = (threadIdx.x >= d) ? s[threadIdx.x - d] : 0;
        __syncthreads();
        s[threadIdx.x] += t;
        __syncthreads();
    }
    if (threadIdx.x < NB) g_boff[threadIdx.x] = s[threadIdx.x] - v;
}
__global__ void scan3_kernel() {
    int i = blockIdx.x * SCAN_B + threadIdx.x;
    if (i < N_NODES) {
        int o = g_off[i] + g_boff[blockIdx.x];
        g_off[i] = o;
        g_cur[i] = o;
    }
    if (i == 0) g_off[N_NODES] = N_EDGES;
}
__global__ void fill_kernel(const int* __restrict__ edge_row,
                            const int* __restrict__ edge_col,
                            const float* __restrict__ edge_val) {
    int e = blockIdx.x * blockDim.x + threadIdx.x;
    if (e >= N_EDGES) return;
    int r = edge_row[e];
    int pos = atomicAdd(&g_cur[r], 1);
    g_csr[pos] = make_int2(edge_col[e], __float_as_int(edge_val[e]));
}

// ---------------------------------------------------------------------------
// Gather-aggregate: one warp per node.  out[r] = sum v_e * y[c_e] + b
// ---------------------------------------------------------------------------
__global__ void __launch_bounds__(256) gather_kernel(
    const float* __restrict__ bias,
    float* __restrict__ out)
{
    int w    = (int)((blockIdx.x * (unsigned)blockDim.x + threadIdx.x) >> 5);
    int lane = threadIdx.x & 31;
    if (w >= N_NODES) return;

    int start = g_off[w];
    int end   = g_off[w + 1];

    float a[8];
#pragma unroll
    for (int j = 0; j < 8; j++) a[j] = 0.f;

    int e = start;
    for (; e + 4 <= end; e += 4) {
        int2 p0 = g_csr[e],     p1 = g_csr[e + 1];
        int2 p2 = g_csr[e + 2], p3 = g_csr[e + 3];
        uint4 q0 = reinterpret_cast<const uint4*>(g_y + (size_t)p0.x * D)[lane];
        uint4 q1 = reinterpret_cast<const uint4*>(g_y + (size_t)p1.x * D)[lane];
        uint4 q2 = reinterpret_cast<const uint4*>(g_y + (size_t)p2.x * D)[lane];
        uint4 q3 = reinterpret_cast<const uint4*>(g_y + (size_t)p3.x * D)[lane];
        float v0 = __int_as_float(p0.y), v1 = __int_as_float(p1.y);
        float v2 = __int_as_float(p2.y), v3 = __int_as_float(p3.y);
#define ACC_Q(q, v) do {                                                       \
        float2 f0 = __half22float2(*reinterpret_cast<const __half2*>(&(q).x)); \
        float2 f1 = __half22float2(*reinterpret_cast<const __half2*>(&(q).y)); \
        float2 f2 = __half22float2(*reinterpret_cast<const __half2*>(&(q).z)); \
        float2 f3 = __half22float2(*reinterpret_cast<const __half2*>(&(q).w)); \
        a[0] += (v) * f0.x; a[1] += (v) * f0.y;                                \
        a[2] += (v) * f1.x; a[3] += (v) * f1.y;                                \
        a[4] += (v) * f2.x; a[5] += (v) * f2.y;                                \
        a[6] += (v) * f3.x; a[7] += (v) * f3.y; } while (0)
        ACC_Q(q0, v0); ACC_Q(q1, v1); ACC_Q(q2, v2); ACC_Q(q3, v3);
    }
    for (; e < end; e++) {
        int2 p = g_csr[e];
        uint4 q = reinterpret_cast<const uint4*>(g_y + (size_t)p.x * D)[lane];
        float v = __int_as_float(p.y);
        ACC_Q(q, v);
    }
#undef ACC_Q

    const float4* bp = reinterpret_cast<const float4*>(bias + lane * 8);
    float4 b0 = bp[0], b1 = bp[1];
    float4 o0 = make_float4(a[0] + b0.x, a[1] + b0.y, a[2] + b0.z, a[3] + b0.w);
    float4 o1 = make_float4(a[4] + b1.x, a[5] + b1.y, a[6] + b1.z, a[7] + b1.w);
    float4* op = reinterpret_cast<float4*>(out + (size_t)w * D + lane * 8);
    op[0] = o0;
    op[1] = o1;
}

// ---------------------------------------------------------------------------
// Launch
// ---------------------------------------------------------------------------
extern "C" void kernel_launch(void* const* d_in, const int* in_sizes, int n_in,
                              void* d_out, int out_size) {
    const float* x        = (const float*)d_in[0];
    const int*   edge_row = (const int*)  d_in[1];
    const int*   edge_col = (const int*)  d_in[2];
    const float* edge_val = (const float*)d_in[3];
    const float* W        = (const float*)d_in[4];
    const float* b        = (const float*)d_in[5];
    float*       out      = (float*)d_out;

    // 0) W -> bf16 hi/lo
    conv_w_kernel<<<(D * D / 4) / 256, 256>>>(W);

    // 1) GEMM: y = fp16(x @ W^T)
    static bool attr_set = false;
    if (!attr_set) {
        cudaFuncSetAttribute(gemm_mma_kernel,
                             cudaFuncAttributeMaxDynamicSharedMemorySize, GEMM_SMEM);
        attr_set = true;
    }
    {
        dim3 grid(D / 128, (N_NODES + 127) / 128);   // (2, 782)
        gemm_mma_kernel<<<grid, 256, GEMM_SMEM>>>(x);
    }
    // 2) CSR build
    zero_cnt_kernel<<<(N_NODES + 255) / 256, 256>>>();
    hist_kernel<<<(N_EDGES + 255) / 256, 256>>>(edge_row);
    scan1_kernel<<<NB, SCAN_B>>>();
    scan2_kernel<<<1, 128>>>();
    scan3_kernel<<<NB, SCAN_B>>>();
    fill_kernel<<<(N_EDGES + 255) / 256, 256>>>(edge_row, edge_col, edge_val);
    // 3) Gather-aggregate + bias -> out
    gather_kernel<<<(N_NODES + 7) / 8, 256>>>(b, out);
}

// round 7
// speedup vs baseline: 3.5990x; 1.0319x over previous
#include <cuda_runtime.h>
#include <cuda_bf16.h>
#include <cuda_fp16.h>
#include <cstdint>

#define N_NODES 100000
#define N_EDGES 3200000
#define D 256
#define SCAN_B 1024
#define NB ((N_NODES + SCAN_B - 1) / SCAN_B)   // 98

// ---------------------------------------------------------------------------
// Scratch (static device allocations only)
// ---------------------------------------------------------------------------
__device__ __half        g_y[(size_t)N_NODES * D];   // y = x @ W^T (fp16, 51.2 MB)
__device__ __nv_bfloat16 g_Whi[D * D];               // W split hi (128 KB)
__device__ __nv_bfloat16 g_Wlo[D * D];               // W split lo (128 KB)
__device__ int2          g_csr[N_EDGES];
__device__ int           g_cnt[N_NODES];
__device__ int           g_off[N_NODES + 1];
__device__ int           g_cur[N_NODES];
__device__ int           g_bsum[NB];
__device__ int           g_boff[NB];

__device__ __forceinline__ uint32_t smem_u32(const void* p) {
    uint32_t a;
    asm("{ .reg .u64 t; cvta.to.shared.u64 t, %1; cvt.u32.u64 %0, t; }"
        : "=r"(a) : "l"(p));
    return a;
}

#define LDM_X4(r, a)                                                        \
    asm volatile("ldmatrix.sync.aligned.m8n8.x4.shared.b16 "                \
                 "{%0,%1,%2,%3}, [%4];"                                     \
                 : "=r"((r)[0]), "=r"((r)[1]), "=r"((r)[2]), "=r"((r)[3])   \
                 : "r"(a))

#define MMA_BF16(c, a, b0, b1)                                              \
    asm volatile("mma.sync.aligned.m16n8k16.row.col.f32.bf16.bf16.f32 "     \
                 "{%0,%1,%2,%3}, {%4,%5,%6,%7}, {%8,%9}, {%0,%1,%2,%3};"    \
                 : "+f"((c)[0]), "+f"((c)[1]), "+f"((c)[2]), "+f"((c)[3])   \
                 : "r"((a)[0]), "r"((a)[1]), "r"((a)[2]), "r"((a)[3]),      \
                   "r"(b0), "r"(b1))

__device__ __forceinline__ uint32_t pack2bf(__nv_bfloat16 e0, __nv_bfloat16 e1) {
    return ((uint32_t)__bfloat16_as_ushort(e1) << 16) | __bfloat16_as_ushort(e0);
}

// ---------------------------------------------------------------------------
// W -> bf16 hi/lo precompute (one-shot, 256 KB read)
// ---------------------------------------------------------------------------
__global__ void conv_w_kernel(const float* __restrict__ W) {
    int i = blockIdx.x * blockDim.x + threadIdx.x;     // one float4 each
    float4 v = reinterpret_cast<const float4*>(W)[i];
    __nv_bfloat16 h0 = __float2bfloat16(v.x), h1 = __float2bfloat16(v.y);
    __nv_bfloat16 h2 = __float2bfloat16(v.z), h3 = __float2bfloat16(v.w);
    __nv_bfloat16 l0 = __float2bfloat16(v.x - __bfloat162float(h0));
    __nv_bfloat16 l1 = __float2bfloat16(v.y - __bfloat162float(h1));
    __nv_bfloat16 l2 = __float2bfloat16(v.z - __bfloat162float(h2));
    __nv_bfloat16 l3 = __float2bfloat16(v.w - __bfloat162float(h3));
    reinterpret_cast<uint2*>(g_Whi)[i] = make_uint2(pack2bf(h0, h1), pack2bf(h2, h3));
    reinterpret_cast<uint2*>(g_Wlo)[i] = make_uint2(pack2bf(l0, l1), pack2bf(l2, l3));
}

// ---------------------------------------------------------------------------
// GEMM: g_y = fp16( x @ W^T )  via mma.sync bf16 hi/lo, double-buffered.
// ---------------------------------------------------------------------------
#define APITCH 40                     // halves per smem row (32 data + 8 pad)
#define TILE_H (128 * APITCH)         // halves per tile
#define GEMM_SMEM (8 * TILE_H * 2)    // 2 stages x 4 tiles x 10240 B = 81920 B

__global__ void __launch_bounds__(256) gemm_mma_kernel(
    const float* __restrict__ x)
{
    extern __shared__ __align__(16) __nv_bfloat16 smem[];
    __nv_bfloat16* sAhi[2] = { smem,              smem + 4 * TILE_H };
    __nv_bfloat16* sAlo[2] = { smem + 1 * TILE_H, smem + 5 * TILE_H };
    __nv_bfloat16* sBhi[2] = { smem + 2 * TILE_H, smem + 6 * TILE_H };
    __nv_bfloat16* sBlo[2] = { smem + 3 * TILE_H, smem + 7 * TILE_H };

    const int tid  = threadIdx.x;
    const int wid  = tid >> 5;
    const int lane = tid & 31;
    const int bm   = blockIdx.y * 128;
    const int bn   = blockIdx.x * 128;
    const int wm   = wid & 1;
    const int wn   = wid >> 1;

    float acc[4][4][4];
#pragma unroll
    for (int i = 0; i < 4; i++)
#pragma unroll
        for (int j = 0; j < 4; j++)
#pragma unroll
            for (int q = 0; q < 4; q++) acc[i][j][q] = 0.f;

    const int seg   = tid & 7;
    const int rbase = tid >> 3;

    float4 va[4];
    uint2  vbh[4], vbl[4];

#define PREFETCH(kc) do {                                                     \
        const int gk = (kc) * 32 + seg * 4;                                   \
        _Pragma("unroll")                                                     \
        for (int t = 0; t < 4; t++) {                                         \
            int row  = t * 32 + rbase;                                        \
            int grow = bm + row;                                              \
            if (grow >= N_NODES) grow = N_NODES - 1;                          \
            va[t] = *reinterpret_cast<const float4*>(x + (size_t)grow * D + gk); \
            size_t wo = ((size_t)(bn + row) * D + gk) >> 2;                   \
            vbh[t] = reinterpret_cast<const uint2*>(g_Whi)[wo];               \
            vbl[t] = reinterpret_cast<const uint2*>(g_Wlo)[wo];               \
        }                                                                     \
    } while (0)

    PREFETCH(0);

    for (int kc = 0; kc < 8; kc++) {
        const int buf = kc & 1;

#pragma unroll
        for (int t = 0; t < 4; t++) {
            int row = t * 32 + rbase;
            int off = row * APITCH + seg * 4;
            float4 v = va[t];
            __nv_bfloat16 h0 = __float2bfloat16(v.x), h1 = __float2bfloat16(v.y);
            __nv_bfloat16 h2 = __float2bfloat16(v.z), h3 = __float2bfloat16(v.w);
            __nv_bfloat16 l0 = __float2bfloat16(v.x - __bfloat162float(h0));
            __nv_bfloat16 l1 = __float2bfloat16(v.y - __bfloat162float(h1));
            __nv_bfloat16 l2 = __float2bfloat16(v.z - __bfloat162float(h2));
            __nv_bfloat16 l3 = __float2bfloat16(v.w - __bfloat162float(h3));
            *reinterpret_cast<uint2*>(sAhi[buf] + off) = make_uint2(pack2bf(h0, h1), pack2bf(h2, h3));
            *reinterpret_cast<uint2*>(sAlo[buf] + off) = make_uint2(pack2bf(l0, l1), pack2bf(l2, l3));
            *reinterpret_cast<uint2*>(sBhi[buf] + off) = vbh[t];
            *reinterpret_cast<uint2*>(sBlo[buf] + off) = vbl[t];
        }
        __syncthreads();

        if (kc < 7) PREFETCH(kc + 1);

        const uint32_t uAhi = smem_u32(sAhi[buf]);
        const uint32_t uAlo = smem_u32(sAlo[buf]);
        const uint32_t uBhi = smem_u32(sBhi[buf]);
        const uint32_t uBlo = smem_u32(sBlo[buf]);
        const int mat  = lane >> 3;
        const int lrow = lane & 7;
#pragma unroll
        for (int ks = 0; ks < 2; ks++) {
            const int kk = ks * 16;
            uint32_t ahi[4][4], alo[4][4], bhi[2][4], blo[2][4];
#pragma unroll
            for (int mt = 0; mt < 4; mt++) {
                int r = wm * 64 + mt * 16 + (mat & 1) * 8 + lrow;
                int c = kk + (mat >> 1) * 8;
                uint32_t bo = (uint32_t)(r * APITCH + c) * 2;
                LDM_X4(ahi[mt], uAhi + bo);
                LDM_X4(alo[mt], uAlo + bo);
            }
#pragma unroll
            for (int p = 0; p < 2; p++) {
                int r = wn * 32 + p * 16 + (mat >> 1) * 8 + lrow;
                int c = kk + (mat & 1) * 8;
                uint32_t bo = (uint32_t)(r * APITCH + c) * 2;
                LDM_X4(bhi[p], uBhi + bo);
                LDM_X4(blo[p], uBlo + bo);
            }
#pragma unroll
            for (int mt = 0; mt < 4; mt++)
#pragma unroll
                for (int p = 0; p < 2; p++)
#pragma unroll
                    for (int h = 0; h < 2; h++) {
                        int nt = p * 2 + h;
                        uint32_t b0h = bhi[p][h * 2], b1h = bhi[p][h * 2 + 1];
                        uint32_t b0l = blo[p][h * 2], b1l = blo[p][h * 2 + 1];
                        MMA_BF16(acc[mt][nt], ahi[mt], b0h, b1h);
                        MMA_BF16(acc[mt][nt], alo[mt], b0h, b1h);
                        MMA_BF16(acc[mt][nt], ahi[mt], b0l, b1l);
                    }
        }
    }
#undef PREFETCH

    const int gr = lane >> 2;
    const int gc = (lane & 3) * 2;
#pragma unroll
    for (int mt = 0; mt < 4; mt++) {
        int m0 = bm + wm * 64 + mt * 16 + gr;
#pragma unroll
        for (int nt = 0; nt < 4; nt++) {
            int n = bn + wn * 32 + nt * 8 + gc;
            if (m0 < N_NODES) {
                __half2 h = __floats2half2_rn(acc[mt][nt][0], acc[mt][nt][1]);
                *reinterpret_cast<__half2*>(g_y + (size_t)m0 * D + n) = h;
            }
            if (m0 + 8 < N_NODES) {
                __half2 h = __floats2half2_rn(acc[mt][nt][2], acc[mt][nt][3]);
                *reinterpret_cast<__half2*>(g_y + (size_t)(m0 + 8) * D + n) = h;
            }
        }
    }
}

// ---------------------------------------------------------------------------
// CSR construction
// ---------------------------------------------------------------------------
__global__ void zero_cnt_kernel() {
    int i = blockIdx.x * blockDim.x + threadIdx.x;
    if (i < N_NODES) g_cnt[i] = 0;
}
__global__ void hist_kernel(const int* __restrict__ edge_row) {
    int e = blockIdx.x * blockDim.x + threadIdx.x;
    if (e < N_EDGES) atomicAdd(&g_cnt[edge_row[e]], 1);
}
__global__ void scan1_kernel() {
    __shared__ int s[SCAN_B];
    int i = blockIdx.x * SCAN_B + threadIdx.x;
    int v = (i < N_NODES) ? g_cnt[i] : 0;
    s[threadIdx.x] = v;
    __syncthreads();
#pragma unroll
    for (int d = 1; d < SCAN_B; d <<= 1) {
        int t = (threadIdx.x >= d) ? s[threadIdx.x - d] : 0;
        __syncthreads();
        s[threadIdx.x] += t;
        __syncthreads();
    }
    if (i < N_NODES) g_off[i] = s[threadIdx.x] - v;
    if (threadIdx.x == SCAN_B - 1) g_bsum[blockIdx.x] = s[SCAN_B - 1];
}
__global__ void scan2_kernel() {
    __shared__ int s[128];
    int v = (threadIdx.x < NB) ? g_bsum[threadIdx.x] : 0;
    s[threadIdx.x] = v;
    __syncthreads();
#pragma unroll
    for (int d = 1; d < 128; d <<= 1) {
        int t = (threadIdx.x >= d) ? s[threadIdx.x - d] : 0;
        __syncthreads();
        s[threadIdx.x] += t;
        __syncthreads();
    }
    if (threadIdx.x < NB) g_boff[threadIdx.x] = s[threadIdx.x] - v;
}
__global__ void scan3_kernel() {
    int i = blockIdx.x * SCAN_B + threadIdx.x;
    if (i < N_NODES) {
        int o = g_off[i] + g_boff[blockIdx.x];
        g_off[i] = o;
        g_cur[i] = o;
    }
    if (i == 0) g_off[N_NODES] = N_EDGES;
}
__global__ void fill_kernel(const int* __restrict__ edge_row,
                            const int* __restrict__ edge_col,
                            const float* __restrict__ edge_val) {
    int e = blockIdx.x * blockDim.x + threadIdx.x;
    if (e >= N_EDGES) return;
    int r = edge_row[e];
    int pos = atomicAdd(&g_cur[r], 1);
    g_csr[pos] = make_int2(edge_col[e], __float_as_int(edge_val[e]));
}

// ---------------------------------------------------------------------------
// Gather-aggregate: one warp per node.  out[r] = sum v_e * y[c_e] + b
// ---------------------------------------------------------------------------
__global__ void __launch_bounds__(256) gather_kernel(
    const float* __restrict__ bias,
    float* __restrict__ out)
{
    int w    = (int)((blockIdx.x * (unsigned)blockDim.x + threadIdx.x) >> 5);
    int lane = threadIdx.x & 31;
    if (w >= N_NODES) return;

    int start = g_off[w];
    int end   = g_off[w + 1];

    float a[8];
#pragma unroll
    for (int j = 0; j < 8; j++) a[j] = 0.f;

    int e = start;
    for (; e + 4 <= end; e += 4) {
        int2 p0 = g_csr[e],     p1 = g_csr[e + 1];
        int2 p2 = g_csr[e + 2], p3 = g_csr[e + 3];
        uint4 q0 = reinterpret_cast<const uint4*>(g_y + (size_t)p0.x * D)[lane];
        uint4 q1 = reinterpret_cast<const uint4*>(g_y + (size_t)p1.x * D)[lane];
        uint4 q2 = reinterpret_cast<const uint4*>(g_y + (size_t)p2.x * D)[lane];
        uint4 q3 = reinterpret_cast<const uint4*>(g_y + (size_t)p3.x * D)[lane];
        float v0 = __int_as_float(p0.y), v1 = __int_as_float(p1.y);
        float v2 = __int_as_float(p2.y), v3 = __int_as_float(p3.y);
#define ACC_Q(q, v) do {                                                       \
        float2 f0 = __half22float2(*reinterpret_cast<const __half2*>(&(q).x)); \
        float2 f1 = __half22float2(*reinterpret_cast<const __half2*>(&(q).y)); \
        float2 f2 = __half22float2(*reinterpret_cast<const __half2*>(&(q).z)); \
        float2 f3 = __half22float2(*reinterpret_cast<const __half2*>(&(q).w)); \
        a[0] += (v) * f0.x; a[1] += (v) * f0.y;                                \
        a[2] += (v) * f1.x; a[3] += (v) * f1.y;                                \
        a[4] += (v) * f2.x; a[5] += (v) * f2.y;                                \
        a[6] += (v) * f3.x; a[7] += (v) * f3.y; } while (0)
        ACC_Q(q0, v0); ACC_Q(q1, v1); ACC_Q(q2, v2); ACC_Q(q3, v3);
    }
    for (; e < end; e++) {
        int2 p = g_csr[e];
        uint4 q = reinterpret_cast<const uint4*>(g_y + (size_t)p.x * D)[lane];
        float v = __int_as_float(p.y);
        ACC_Q(q, v);
    }
#undef ACC_Q

    const float4* bp = reinterpret_cast<const float4*>(bias + lane * 8);
    float4 b0 = bp[0], b1 = bp[1];
    float4 o0 = make_float4(a[0] + b0.x, a[1] + b0.y, a[2] + b0.z, a[3] + b0.w);
    float4 o1 = make_float4(a[4] + b1.x, a[5] + b1.y, a[6] + b1.z, a[7] + b1.w);
    float4* op = reinterpret_cast<float4*>(out + (size_t)w * D + lane * 8);
    op[0] = o0;
    op[1] = o1;
}

// ---------------------------------------------------------------------------
// Launch: fork GEMM chain and CSR chain into parallel graph branches.
//   main: conv_w -> gemm ----------------\
//   s2:   zero -> hist -> scans -> fill --+--> gather (main)
// Event record/wait inside capture creates graph dependencies; stream/event
// creation happens once (static init, no device memory involved).
// ---------------------------------------------------------------------------
extern "C" void kernel_launch(void* const* d_in, const int* in_sizes, int n_in,
                              void* d_out, int out_size) {
    const float* x        = (const float*)d_in[0];
    const int*   edge_row = (const int*)  d_in[1];
    const int*   edge_col = (const int*)  d_in[2];
    const float* edge_val = (const float*)d_in[3];
    const float* W        = (const float*)d_in[4];
    const float* b        = (const float*)d_in[5];
    float*       out      = (float*)d_out;

    static cudaStream_t s2 = nullptr;
    static cudaEvent_t  evFork = nullptr, evJoin = nullptr;
    if (s2 == nullptr) {
        cudaStreamCreateWithFlags(&s2, cudaStreamNonBlocking);
        cudaEventCreateWithFlags(&evFork, cudaEventDisableTiming);
        cudaEventCreateWithFlags(&evJoin, cudaEventDisableTiming);
        cudaFuncSetAttribute(gemm_mma_kernel,
                             cudaFuncAttributeMaxDynamicSharedMemorySize, GEMM_SMEM);
    }

    // fork
    cudaEventRecord(evFork, 0);
    cudaStreamWaitEvent(s2, evFork, 0);

    // Branch A (default stream): W split + GEMM
    conv_w_kernel<<<(D * D / 4) / 256, 256>>>(W);
    {
        dim3 grid(D / 128, (N_NODES + 127) / 128);   // (2, 782)
        gemm_mma_kernel<<<grid, 256, GEMM_SMEM>>>(x);
    }

    // Branch B (s2): CSR build
    zero_cnt_kernel<<<(N_NODES + 255) / 256, 256, 0, s2>>>();
    hist_kernel<<<(N_EDGES + 255) / 256, 256, 0, s2>>>(edge_row);
    scan1_kernel<<<NB, SCAN_B, 0, s2>>>();
    scan2_kernel<<<1, 128, 0, s2>>>();
    scan3_kernel<<<NB, SCAN_B, 0, s2>>>();
    fill_kernel<<<(N_EDGES + 255) / 256, 256, 0, s2>>>(edge_row, edge_col, edge_val);

    // join
    cudaEventRecord(evJoin, s2);
    cudaStreamWaitEvent(0, evJoin, 0);

    // Gather-aggregate + bias -> out (needs both branches)
    gather_kernel<<<(N_NODES + 7) / 8, 256>>>(b, out);
}